// round 7
// baseline (speedup 1.0000x reference)
#include <cuda_runtime.h>
#include <cuda_bf16.h>
#include <cstdint>

#define N 4096
#define DF 64

// Scratch (allocation-free rule: __device__ globals)
__device__ float g_D[(size_t)N * N];   // 64 MB distance matrix, diagonal = +inf
__device__ float g_sq[N];              // squared norms

__device__ __forceinline__ float finf() { return __int_as_float(0x7f800000); }

// ---------------------------------------------------------------------------
// Kernel 0: squared norms
// ---------------------------------------------------------------------------
__global__ void sq_kernel(const float* __restrict__ x) {
    int i = blockIdx.x * blockDim.x + threadIdx.x;
    if (i >= N) return;
    const float4* xi = (const float4*)(x + (size_t)i * DF);
    float s = 0.f;
#pragma unroll
    for (int k = 0; k < DF / 4; k++) {
        float4 v = xi[k];
        s += v.x * v.x + v.y * v.y + v.z * v.z + v.w * v.w;
    }
    g_sq[i] = s;
}

// ---------------------------------------------------------------------------
// Kernel 1: distance matrix, 64x64 tiles, 256 threads, 4x4 per thread.
// ---------------------------------------------------------------------------
__global__ __launch_bounds__(256) void dist_kernel(const float* __restrict__ x) {
    __shared__ __align__(16) float sA[DF * 68];
    __shared__ __align__(16) float sB[DF * 68];

    const int t    = threadIdx.x;
    const int lrow = t >> 2;      // 0..63
    const int q    = t & 3;       // 0..3
    const int i0   = blockIdx.y * 64;
    const int j0   = blockIdx.x * 64;

    {
        const float4* xa = (const float4*)(x + (size_t)(i0 + lrow) * DF) + q * 4;
        const float4* xb = (const float4*)(x + (size_t)(j0 + lrow) * DF) + q * 4;
#pragma unroll
        for (int u = 0; u < 4; u++) {
            float4 va = xa[u];
            float4 vb = xb[u];
            int k0 = q * 16 + u * 4;
            sA[(k0 + 0) * 68 + lrow] = va.x;
            sA[(k0 + 1) * 68 + lrow] = va.y;
            sA[(k0 + 2) * 68 + lrow] = va.z;
            sA[(k0 + 3) * 68 + lrow] = va.w;
            sB[(k0 + 0) * 68 + lrow] = vb.x;
            sB[(k0 + 1) * 68 + lrow] = vb.y;
            sB[(k0 + 2) * 68 + lrow] = vb.z;
            sB[(k0 + 3) * 68 + lrow] = vb.w;
        }
    }
    __syncthreads();

    const int tx = t & 15;
    const int ty = t >> 4;

    float acc[4][4];
#pragma unroll
    for (int r = 0; r < 4; r++)
#pragma unroll
        for (int c = 0; c < 4; c++) acc[r][c] = 0.f;

#pragma unroll 8
    for (int k = 0; k < DF; k++) {
        float4 a = *(const float4*)&sA[k * 68 + ty * 4];
        float4 b = *(const float4*)&sB[k * 68 + tx * 4];
        float av[4] = {a.x, a.y, a.z, a.w};
        float bv[4] = {b.x, b.y, b.z, b.w};
#pragma unroll
        for (int r = 0; r < 4; r++)
#pragma unroll
            for (int c = 0; c < 4; c++) acc[r][c] = fmaf(av[r], bv[c], acc[r][c]);
    }

    float sqI[4], sqJ[4];
#pragma unroll
    for (int r = 0; r < 4; r++) sqI[r] = g_sq[i0 + ty * 4 + r];
#pragma unroll
    for (int c = 0; c < 4; c++) sqJ[c] = g_sq[j0 + tx * 4 + c];

#pragma unroll
    for (int r = 0; r < 4; r++) {
        int gi = i0 + ty * 4 + r;
        float4 o;
        float ov[4];
#pragma unroll
        for (int c = 0; c < 4; c++) {
            int gj = j0 + tx * 4 + c;
            float d2 = sqI[r] + sqJ[c] - 2.f * acc[r][c];
            float d  = sqrtf(fmaxf(d2, 1e-12f));
            ov[c] = (gi == gj) ? finf() : d;
        }
        o.x = ov[0]; o.y = ov[1]; o.z = ov[2]; o.w = ov[3];
        *(float4*)(g_D + (size_t)gi * N + j0 + tx * 4) = o;
    }
}

// ---------------------------------------------------------------------------
// Kernel 2: Prim scan. Single CTA, 256 threads (8 warps), 16 elems/thread.
//
// Element mapping: global idx = wid*512 + q*128 + lane*4 + c  (e = q*4+c).
// Per-thread state:
//   m[e]     : running min distance (fminf-updated; OFF the critical path)
//   msent[e] : 0 normally, 0xFFFFFFFF once in-tree (OR-mask sorts it last
//              under unsigned compare on float bits — all distances > 0)
//   (cv,ci)  : cached per-thread argmin key of masked m (value bits, global
//              index). Updated incrementally = min(cached, tree(masked dv)).
//              Invalidated only when THIS thread's cached elem joins the tree;
//              recomputed then under the next row-load's latency shadow.
//
// Global reduce: per-warp REDUX(value) + REDUX(index) -> lane0 atomicMin of
// the packed u64 key (value<<32|index; unsigned min == first-occurrence
// argmin, matching jnp.argmin) into a shared slot. One BAR, one LDS.64
// broadcast. Slots are triple-buffered; slot (s+2)%3 is re-initialized at
// step s (its last readers finished before BAR(s); its next writers start
// after BAR(s+1)) — race-free by the barrier ordering.
// ---------------------------------------------------------------------------
__global__ __launch_bounds__(256, 1) void prim_kernel(float* __restrict__ out) {
    __shared__ unsigned long long s_slot[3];

    const int tid  = threadIdx.x;
    const int lane = tid & 31;
    const int wid  = tid >> 5;
    const int base = wid * 512 + lane * 4;   // global idx of e=0

    // loop-invariant global indices for the 16 owned elements
    unsigned gidx[16];
#pragma unroll
    for (int e = 0; e < 16; e++) gidx[e] = (unsigned)(base + ((e >> 2) << 7) + (e & 3));

    float    m[16];
    unsigned msent[16];
#pragma unroll
    for (int e = 0; e < 16; e++) { m[e] = finf(); msent[e] = 0u; }
    if (tid == 0) msent[0] = 0xFFFFFFFFu;    // vertex 0 starts in the tree

    unsigned cv = 0x7f800000u;               // cached key: +inf bits
    unsigned ci = gidx[0];
    bool     pend = false;

    if (tid == 0) {
        s_slot[0] = 0xffffffffffffffffull;
        s_slot[1] = 0xffffffffffffffffull;
        s_slot[2] = 0xffffffffffffffffull;
    }
    __syncthreads();

    int j = 0;
    int p = 0;                                // step % 3

    for (int step = 0; step < N - 1; step++) {
        // ---- issue row loads first (MLP=4), everything else hides under them
        const float4* rp = (const float4*)(g_D + ((size_t)j << 12)) + wid * 128 + lane;
        float4 q0 = __ldcg(rp);
        float4 q1 = __ldcg(rp + 32);
        float4 q2 = __ldcg(rp + 64);
        float4 q3 = __ldcg(rp + 96);

        // ---- rebuild cached argmin if our cached elem joined the tree
        //      (runs under the LDG shadow; one thread per step at most)
        if (pend) {
            unsigned u[16];
#pragma unroll
            for (int e = 0; e < 16; e++) u[e] = __float_as_uint(m[e]) | msent[e];
            unsigned tv2[8], ti2[8];
#pragma unroll
            for (int k = 0; k < 8; k++) {
                bool s = u[2 * k + 1] < u[2 * k];
                tv2[k] = s ? u[2 * k + 1] : u[2 * k];
                ti2[k] = s ? gidx[2 * k + 1] : gidx[2 * k];
            }
#pragma unroll
            for (int k = 0; k < 4; k++) {
                bool s = tv2[2 * k + 1] < tv2[2 * k];
                tv2[k] = s ? tv2[2 * k + 1] : tv2[2 * k];
                ti2[k] = s ? ti2[2 * k + 1] : ti2[2 * k];
            }
#pragma unroll
            for (int k = 0; k < 2; k++) {
                bool s = tv2[2 * k + 1] < tv2[2 * k];
                tv2[k] = s ? tv2[2 * k + 1] : tv2[2 * k];
                ti2[k] = s ? ti2[2 * k + 1] : ti2[2 * k];
            }
            bool s0 = tv2[1] < tv2[0];
            cv = s0 ? tv2[1] : tv2[0];
            ci = s0 ? ti2[1] : ti2[0];
            pend = false;
        }

        float dv[16] = {q0.x, q0.y, q0.z, q0.w, q1.x, q1.y, q1.z, q1.w,
                        q2.x, q2.y, q2.z, q2.w, q3.x, q3.y, q3.z, q3.w};

        // ---- critical path: mask incoming row, tree-argmin, merge cached
        unsigned v[16];
#pragma unroll
        for (int e = 0; e < 16; e++) v[e] = __float_as_uint(dv[e]) | msent[e];

        unsigned bv[8], bi[8];
#pragma unroll
        for (int k = 0; k < 8; k++) {
            bool s = v[2 * k + 1] < v[2 * k];
            bv[k] = s ? v[2 * k + 1] : v[2 * k];
            bi[k] = s ? gidx[2 * k + 1] : gidx[2 * k];
        }
#pragma unroll
        for (int k = 0; k < 4; k++) {
            bool s = bv[2 * k + 1] < bv[2 * k];
            bv[k] = s ? bv[2 * k + 1] : bv[2 * k];
            bi[k] = s ? bi[2 * k + 1] : bi[2 * k];
        }
#pragma unroll
        for (int k = 0; k < 2; k++) {
            bool s = bv[2 * k + 1] < bv[2 * k];
            bv[k] = s ? bv[2 * k + 1] : bv[2 * k];
            bi[k] = s ? bi[2 * k + 1] : bi[2 * k];
        }
        bool s0 = bv[1] < bv[0];
        unsigned tv = s0 ? bv[1] : bv[0];
        unsigned ti = s0 ? bi[1] : bi[0];

        // merged = min(cached_key, new_key)  (value, then index)
        bool takenew = (tv < cv) || (tv == cv && ti < ci);
        cv = takenew ? tv : cv;
        ci = takenew ? ti : ci;

        // ---- warp argmin via two REDUX, then one atomic per warp
        unsigned wmin = __reduce_min_sync(0xffffffffu, cv);
        unsigned cand = (cv == wmin) ? ci : 0xffffffffu;
        unsigned widx = __reduce_min_sync(0xffffffffu, cand);
        if (lane == 0)
            atomicMin(&s_slot[p], ((unsigned long long)wmin << 32) | widx);

        // ---- off-critical-path: update running mins for future steps
#pragma unroll
        for (int e = 0; e < 16; e++) m[e] = fminf(m[e], dv[e]);

        __syncthreads();

        unsigned long long k8 = s_slot[p];
        unsigned gi = (unsigned)k8;

        if (tid == 0) {
            *(float2*)(out + 2 * step) =
                make_float2(0.0f, __uint_as_float((unsigned)(k8 >> 32)));
            // re-init the slot used 2 steps ahead (safe: last read before this
            // BAR; next atomics after the next BAR)
            s_slot[p == 0 ? 2 : p - 1] = 0xffffffffffffffffull;
        }

        // ---- winner joins the tree
        int own = (int)(((gi >> 9) << 5) | ((gi >> 2) & 31));
        if (own == tid) {
            int e = (int)(((gi >> 5) & 0xCu) | (gi & 3u));
            msent[e] = 0xFFFFFFFFu;
            if (ci == gi) pend = true;    // cached elem removed -> rebuild
        }

        j = (int)gi;
        p = (p == 2) ? 0 : p + 1;
    }
}

// ---------------------------------------------------------------------------
extern "C" void kernel_launch(void* const* d_in, const int* in_sizes, int n_in,
                              void* d_out, int out_size) {
    const float* x   = (const float*)d_in[0];
    float*       out = (float*)d_out;

    sq_kernel<<<(N + 255) / 256, 256>>>(x);
    dim3 grid(N / 64, N / 64);
    dist_kernel<<<grid, 256>>>(x);
    prim_kernel<<<1, 256>>>(out);
}

// round 8
// speedup vs baseline: 1.1560x; 1.1560x over previous
#include <cuda_runtime.h>
#include <cuda_bf16.h>
#include <cstdint>

#define N 4096
#define DF 64

// Scratch (allocation-free rule: __device__ globals)
__device__ float g_D[(size_t)N * N];   // 64 MB distance matrix, diagonal = +inf
__device__ float g_sq[N];              // squared norms

__device__ __forceinline__ float finf() { return __int_as_float(0x7f800000); }

// ---------------------------------------------------------------------------
// Kernel 0: squared norms
// ---------------------------------------------------------------------------
__global__ void sq_kernel(const float* __restrict__ x) {
    int i = blockIdx.x * blockDim.x + threadIdx.x;
    if (i >= N) return;
    const float4* xi = (const float4*)(x + (size_t)i * DF);
    float s = 0.f;
#pragma unroll
    for (int k = 0; k < DF / 4; k++) {
        float4 v = xi[k];
        s += v.x * v.x + v.y * v.y + v.z * v.z + v.w * v.w;
    }
    g_sq[i] = s;
}

// ---------------------------------------------------------------------------
// Kernel 1: distance matrix, 64x64 tiles, 256 threads, 4x4 per thread.
// ---------------------------------------------------------------------------
__global__ __launch_bounds__(256) void dist_kernel(const float* __restrict__ x) {
    __shared__ __align__(16) float sA[DF * 68];
    __shared__ __align__(16) float sB[DF * 68];

    const int t    = threadIdx.x;
    const int lrow = t >> 2;      // 0..63
    const int q    = t & 3;       // 0..3
    const int i0   = blockIdx.y * 64;
    const int j0   = blockIdx.x * 64;

    {
        const float4* xa = (const float4*)(x + (size_t)(i0 + lrow) * DF) + q * 4;
        const float4* xb = (const float4*)(x + (size_t)(j0 + lrow) * DF) + q * 4;
#pragma unroll
        for (int u = 0; u < 4; u++) {
            float4 va = xa[u];
            float4 vb = xb[u];
            int k0 = q * 16 + u * 4;
            sA[(k0 + 0) * 68 + lrow] = va.x;
            sA[(k0 + 1) * 68 + lrow] = va.y;
            sA[(k0 + 2) * 68 + lrow] = va.z;
            sA[(k0 + 3) * 68 + lrow] = va.w;
            sB[(k0 + 0) * 68 + lrow] = vb.x;
            sB[(k0 + 1) * 68 + lrow] = vb.y;
            sB[(k0 + 2) * 68 + lrow] = vb.z;
            sB[(k0 + 3) * 68 + lrow] = vb.w;
        }
    }
    __syncthreads();

    const int tx = t & 15;
    const int ty = t >> 4;

    float acc[4][4];
#pragma unroll
    for (int r = 0; r < 4; r++)
#pragma unroll
        for (int c = 0; c < 4; c++) acc[r][c] = 0.f;

#pragma unroll 8
    for (int k = 0; k < DF; k++) {
        float4 a = *(const float4*)&sA[k * 68 + ty * 4];
        float4 b = *(const float4*)&sB[k * 68 + tx * 4];
        float av[4] = {a.x, a.y, a.z, a.w};
        float bv[4] = {b.x, b.y, b.z, b.w};
#pragma unroll
        for (int r = 0; r < 4; r++)
#pragma unroll
            for (int c = 0; c < 4; c++) acc[r][c] = fmaf(av[r], bv[c], acc[r][c]);
    }

    float sqI[4], sqJ[4];
#pragma unroll
    for (int r = 0; r < 4; r++) sqI[r] = g_sq[i0 + ty * 4 + r];
#pragma unroll
    for (int c = 0; c < 4; c++) sqJ[c] = g_sq[j0 + tx * 4 + c];

#pragma unroll
    for (int r = 0; r < 4; r++) {
        int gi = i0 + ty * 4 + r;
        float4 o;
        float ov[4];
#pragma unroll
        for (int c = 0; c < 4; c++) {
            int gj = j0 + tx * 4 + c;
            float d2 = sqI[r] + sqJ[c] - 2.f * acc[r][c];
            float d  = sqrtf(fmaxf(d2, 1e-12f));
            ov[c] = (gi == gj) ? finf() : d;
        }
        o.x = ov[0]; o.y = ov[1]; o.z = ov[2]; o.w = ov[3];
        *(float4*)(g_D + (size_t)gi * N + j0 + tx * 4) = o;
    }
}

// ---------------------------------------------------------------------------
// Kernel 2: Prim scan. Single CTA, 256 threads (8 warps), 16 elems/thread
// (R5 structure: register mind, sentinel bit-ordering, REDUX two-stage).
//
// NEW: runner-up speculation. After j is known, the approximate runner-up
// (min over the non-winning per-warp slot keys) predicts the NEXT winner.
// At each loop top, after issuing the critical row-j loads, we compute that
// prediction from the carried slot keys and fire 4 ld.global.ca prefetches
// of the predicted row — warming L1 so a correct prediction turns the next
// step's L2-latency (~250cyc) into an L1 hit (~40cyc). Wrong predictions are
// harmless (off-path work only).
// ---------------------------------------------------------------------------
__global__ __launch_bounds__(256, 1) void prim_kernel(float* __restrict__ out) {
    __shared__ unsigned long long s_warp[2][8];

    const int tid  = threadIdx.x;
    const int lane = tid & 31;
    const int wid  = tid >> 5;
    const int base = wid * 512 + lane * 4;   // global idx of e=0

    float m[16];
#pragma unroll
    for (int e = 0; e < 16; e++) m[e] = finf();
    if (tid == 0) m[0] = -1.0f;   // vertex 0 starts in the tree

    int j   = 0;
    int par = 0;
    // carried state for speculation (slot keys of the previous reduction)
    unsigned long long pk8 = 0xffffffffffffffffull;
    unsigned           pgi = 0xffffffffu;

    for (int step = 0; step < N - 1; step++) {
        // ---- critical loads first (L1-allocating so prefetch can hit)
        const float4* rp = (const float4*)(g_D + ((size_t)j << 12)) + wid * 128 + lane;
        float4 q0 = __ldca(rp);
        float4 q1 = __ldca(rp + 32);
        float4 q2 = __ldca(rp + 64);
        float4 q3 = __ldca(rp + 96);

        // ---- off-path: predict next winner = runner-up of previous slots,
        //      prefetch its row into L1 (fire-and-forget)
        {
            unsigned pv = (unsigned)(pk8 >> 32);
            unsigned vm = ((unsigned)pk8 == pgi) ? 0xffffffffu : pv; // drop winner slot
            unsigned g2 = __reduce_min_sync(0xffffffffu, vm);
            unsigned c3 = (vm == g2) ? (unsigned)pk8 : 0xffffffffu;
            unsigned j2 = __reduce_min_sync(0xffffffffu, c3);
            if (j2 != 0xffffffffu) {
                const float4* pp =
                    (const float4*)(g_D + ((size_t)j2 << 12)) + wid * 128 + lane;
                unsigned a0, a1, a2, a3;
#pragma unroll
                for (int u = 0; u < 4; u++) {
                    asm volatile("ld.global.ca.v4.b32 {%0,%1,%2,%3}, [%4];"
                                 : "=r"(a0), "=r"(a1), "=r"(a2), "=r"(a3)
                                 : "l"(pp + u * 32));
                }
            }
        }

        float dv[16] = {q0.x, q0.y, q0.z, q0.w, q1.x, q1.y, q1.z, q1.w,
                        q2.x, q2.y, q2.z, q2.w, q3.x, q3.y, q3.z, q3.w};

        // ---- merge + mask via sentinel bit-ordering (-1.0f sorts after +inf)
        unsigned v[16];
#pragma unroll
        for (int e = 0; e < 16; e++) {
            m[e] = fminf(m[e], dv[e]);
            v[e] = __float_as_uint(m[e]);
        }

        // ---- local argmin tree (strict < keeps earlier index)
        unsigned bv[8]; int be[8];
#pragma unroll
        for (int k = 0; k < 8; k++) {
            bool p = v[2 * k + 1] < v[2 * k];
            bv[k] = p ? v[2 * k + 1] : v[2 * k];
            be[k] = p ? (2 * k + 1) : (2 * k);
        }
#pragma unroll
        for (int k = 0; k < 4; k++) {
            bool p = bv[2 * k + 1] < bv[2 * k];
            bv[k] = p ? bv[2 * k + 1] : bv[2 * k];
            be[k] = p ? be[2 * k + 1] : be[2 * k];
        }
#pragma unroll
        for (int k = 0; k < 2; k++) {
            bool p = bv[2 * k + 1] < bv[2 * k];
            bv[k] = p ? bv[2 * k + 1] : bv[2 * k];
            be[k] = p ? be[2 * k + 1] : be[2 * k];
        }
        bool p0 = bv[1] < bv[0];
        unsigned myv = p0 ? bv[1] : bv[0];
        int      e0  = p0 ? be[1] : be[0];
        int besti = base + ((e0 >> 2) << 7) + (e0 & 3);

        // ---- stage 1: warp argmin via two REDUX ops
        unsigned wmin = __reduce_min_sync(0xffffffffu, myv);
        unsigned cand = (myv == wmin) ? (unsigned)besti : 0xffffffffu;
        unsigned widx = __reduce_min_sync(0xffffffffu, cand);
        if (lane == 0)
            s_warp[par][wid] = ((unsigned long long)wmin << 32) | widx;
        __syncthreads();

        // ---- stage 2: every warp redundantly reduces the 8 per-warp keys
        unsigned long long k8 =
            (lane < 8) ? s_warp[par][lane] : 0xffffffffffffffffull;
        unsigned kv   = (unsigned)(k8 >> 32);
        unsigned gmin = __reduce_min_sync(0xffffffffu, kv);
        unsigned c2   = (kv == gmin) ? (unsigned)k8 : 0xffffffffu;
        unsigned gi   = __reduce_min_sync(0xffffffffu, c2);

        j   = (int)gi;
        pk8 = k8;      // carry for next-step speculation
        pgi = gi;
        int own = (int)(((gi >> 9) << 5) | ((gi >> 2) & 31));
        if (own == tid) {
            int e = (int)(((gi >> 5) & 0xCu) | (gi & 3u));
            m[e] = -1.0f;   // join tree
        }
        if (tid == 0)
            *(float2*)(out + 2 * step) = make_float2(0.0f, __uint_as_float(gmin));
        par ^= 1;
    }
}

// ---------------------------------------------------------------------------
extern "C" void kernel_launch(void* const* d_in, const int* in_sizes, int n_in,
                              void* d_out, int out_size) {
    const float* x   = (const float*)d_in[0];
    float*       out = (float*)d_out;

    sq_kernel<<<(N + 255) / 256, 256>>>(x);
    dim3 grid(N / 64, N / 64);
    dist_kernel<<<grid, 256>>>(x);
    prim_kernel<<<1, 256>>>(out);
}